// round 4
// baseline (speedup 1.0000x reference)
#include <cuda_runtime.h>
#include <cstdint>

#define NN 50000
#define NE 25000
#define CC 128

// ---- scratch (device globals; no allocation) ----
__device__ __align__(16) float g_esum[NE * CC];   // per-edge sum of gathered x
__device__ __align__(16) float g_t[NE * CC];      // relu(mean @ W1^T + b1)
__device__ __align__(16) float g_e2[NE * CC];     // t @ W2^T + b2
__device__ __align__(16) float g_cnt_e[NE];
__device__ __align__(16) float g_cnt_n[NN];
__device__ __align__(16) float g_WT1[CC * CC];    // W1 transposed: [k][n]
__device__ __align__(16) float g_WT2[CC * CC];    // W2 transposed: [k][n]

// ---- zero accumulators (incl. d_out, which is poisoned) + transpose weights ----
__global__ void prep_kernel(float* __restrict__ out,
                            const float* __restrict__ W1,
                            const float* __restrict__ W2) {
    int tid = blockIdx.x * blockDim.x + threadIdx.x;
    int stride = gridDim.x * blockDim.x;
    float4 z = make_float4(0.f, 0.f, 0.f, 0.f);
    float4* p1 = reinterpret_cast<float4*>(g_esum);
    for (int i = tid; i < NE * CC / 4; i += stride) p1[i] = z;
    float4* p2 = reinterpret_cast<float4*>(out);
    for (int i = tid; i < NN * CC / 4; i += stride) p2[i] = z;
    float4* p3 = reinterpret_cast<float4*>(g_cnt_e);
    for (int i = tid; i < NE / 4; i += stride) p3[i] = z;
    float4* p4 = reinterpret_cast<float4*>(g_cnt_n);
    for (int i = tid; i < NN / 4; i += stride) p4[i] = z;
    // transpose both 128x128 weight matrices
    for (int i = tid; i < CC * CC; i += stride) {
        int n = i >> 7;
        int k = i & 127;
        g_WT1[k * CC + n] = W1[i];
        g_WT2[k * CC + n] = W2[i];
    }
}

// ---- scatter1: x[node] -> esum[edge] via vector reductions; counts too ----
__global__ void scatter1_kernel(const float* __restrict__ x,
                                const int* __restrict__ nidx,
                                const int* __restrict__ eidx, int ninc) {
    int gw = (blockIdx.x * blockDim.x + threadIdx.x) >> 5;
    int lane = threadIdx.x & 31;
    if (gw >= ninc) return;
    int n = __ldg(nidx + gw);
    int e = __ldg(eidx + gw);
    float4 v = *reinterpret_cast<const float4*>(x + (size_t)n * CC + lane * 4);
    float* dst = g_esum + (size_t)e * CC + lane * 4;
    asm volatile("red.global.add.v4.f32 [%0], {%1,%2,%3,%4};"
                 :: "l"(dst), "f"(v.x), "f"(v.y), "f"(v.z), "f"(v.w)
                 : "memory");
    if (lane == 0) {
        atomicAdd(g_cnt_e + e, 1.0f);
        atomicAdd(g_cnt_n + n, 1.0f);
    }
}

// ---- scatter2: e2[edge] -> out[node] ----
__global__ void scatter2_kernel(const int* __restrict__ nidx,
                                const int* __restrict__ eidx,
                                float* __restrict__ out, int ninc) {
    int gw = (blockIdx.x * blockDim.x + threadIdx.x) >> 5;
    int lane = threadIdx.x & 31;
    if (gw >= ninc) return;
    int n = __ldg(nidx + gw);
    int e = __ldg(eidx + gw);
    float4 v = *reinterpret_cast<const float4*>(g_e2 + (size_t)e * CC + lane * 4);
    float* dst = out + (size_t)n * CC + lane * 4;
    asm volatile("red.global.add.v4.f32 [%0], {%1,%2,%3,%4};"
                 :: "l"(dst), "f"(v.x), "f"(v.y), "f"(v.z), "f"(v.w)
                 : "memory");
}

// ---- fused GEMM: out = [relu]( [A/cnt] @ W^T + bias ), M x 128 @ 128 x 128 ----
// STAGE 0: A=g_esum (scaled by 1/cnt_e), W=g_WT1, out=g_t, relu
// STAGE 1: A=g_t, W=g_WT2, out=g_e2, no relu
template <int STAGE>
__global__ void __launch_bounds__(256) gemm_kernel(const float* __restrict__ bias) {
    const float* __restrict__ A  = (STAGE == 0) ? g_esum : g_t;
    const float* __restrict__ WT = (STAGE == 0) ? g_WT1 : g_WT2;
    float* __restrict__ out      = (STAGE == 0) ? g_t : g_e2;
    constexpr bool MEAN = (STAGE == 0);
    constexpr bool RELU = (STAGE == 0);
    const int M = NE;

    __shared__ float As[32][65];                 // [k][m], pad 65 -> conflict-free
    __shared__ __align__(16) float Bs[32][128];  // [k][n], float4 both directions

    const int tid = threadIdx.x;
    const int ty = tid >> 4;   // 0..15 -> 4 rows each
    const int tx = tid & 15;   // 0..15 -> 8 cols each
    const int row0 = blockIdx.x * 64;

    float acc[4][8];
#pragma unroll
    for (int i = 0; i < 4; i++)
#pragma unroll
        for (int j = 0; j < 8; j++) acc[i][j] = 0.f;

    const int ar = tid >> 3;   // 0..31
    const int akq = tid & 7;   // 0..7 (float4 slot within 32-wide k chunk)

    for (int kb = 0; kb < CC; kb += 32) {
        // ---- fill A tile (transposed, with optional per-row 1/cnt scaling) ----
#pragma unroll
        for (int p = 0; p < 2; p++) {
            int r = ar + p * 32;
            int gm = row0 + r;
            float4 v = make_float4(0.f, 0.f, 0.f, 0.f);
            if (gm < M) {
                v = *reinterpret_cast<const float4*>(A + (size_t)gm * CC + kb + akq * 4);
                if (MEAN) {
                    float s = 1.f / fmaxf(g_cnt_e[gm], 1.f);
                    v.x *= s; v.y *= s; v.z *= s; v.w *= s;
                }
            }
            As[akq * 4 + 0][r] = v.x;
            As[akq * 4 + 1][r] = v.y;
            As[akq * 4 + 2][r] = v.z;
            As[akq * 4 + 3][r] = v.w;
        }
        // ---- fill B tile from pre-transposed W: float4 load + float4 store ----
        {
            int k = tid >> 3;   // 0..31
            int nq = tid & 7;   // 0..7
#pragma unroll
            for (int p = 0; p < 4; p++) {
                int n4 = nq + 8 * p;  // float4 column 0..31
                float4 v = *reinterpret_cast<const float4*>(
                    WT + (size_t)(kb + k) * CC + n4 * 4);
                *reinterpret_cast<float4*>(&Bs[k][n4 * 4]) = v;
            }
        }
        __syncthreads();
#pragma unroll
        for (int k = 0; k < 32; k++) {
            float a[4];
#pragma unroll
            for (int i = 0; i < 4; i++) a[i] = As[k][ty * 4 + i];
            float4 b0 = *reinterpret_cast<float4*>(&Bs[k][tx * 8]);
            float4 b1 = *reinterpret_cast<float4*>(&Bs[k][tx * 8 + 4]);
            float b[8] = {b0.x, b0.y, b0.z, b0.w, b1.x, b1.y, b1.z, b1.w};
#pragma unroll
            for (int i = 0; i < 4; i++)
#pragma unroll
                for (int j = 0; j < 8; j++) acc[i][j] += a[i] * b[j];
        }
        __syncthreads();
    }
    // ---- epilogue ----
#pragma unroll
    for (int i = 0; i < 4; i++) {
        int gm = row0 + ty * 4 + i;
        if (gm < M) {
#pragma unroll
            for (int j = 0; j < 8; j++) {
                int c = tx * 8 + j;
                float v = acc[i][j] + bias[c];
                if (RELU) v = fmaxf(v, 0.f);
                out[(size_t)gm * CC + c] = v;
            }
        }
    }
}

// ---- finalize: out = relu(out / max(cnt_n, 1)) ----
__global__ void finalize_kernel(float* __restrict__ out) {
    int i = blockIdx.x * blockDim.x + threadIdx.x;
    int stride = gridDim.x * blockDim.x;
    float4* p = reinterpret_cast<float4*>(out);
    for (; i < NN * CC / 4; i += stride) {
        int m = i >> 5;  // 32 float4 per row
        float s = 1.f / fmaxf(g_cnt_n[m], 1.f);
        float4 v = p[i];
        v.x = fmaxf(v.x * s, 0.f);
        v.y = fmaxf(v.y * s, 0.f);
        v.z = fmaxf(v.z * s, 0.f);
        v.w = fmaxf(v.w * s, 0.f);
        p[i] = v;
    }
}

extern "C" void kernel_launch(void* const* d_in, const int* in_sizes, int n_in,
                              void* d_out, int out_size) {
    const float* x  = (const float*)d_in[0];
    const int*   hi = (const int*)d_in[1];
    const float* W1 = (const float*)d_in[2];
    const float* b1 = (const float*)d_in[3];
    const float* W2 = (const float*)d_in[4];
    const float* b2 = (const float*)d_in[5];
    float* out = (float*)d_out;

    int ninc = in_sizes[1] / 2;
    const int* nidx = hi;          // hyperedge_index[0]
    const int* eidx = hi + ninc;   // hyperedge_index[1]

    prep_kernel<<<1024, 256>>>(out, W1, W2);
    scatter1_kernel<<<(ninc + 7) / 8, 256>>>(x, nidx, eidx, ninc);
    gemm_kernel<0><<<(NE + 63) / 64, 256>>>(b1);
    gemm_kernel<1><<<(NE + 63) / 64, 256>>>(b2);
    scatter2_kernel<<<(ninc + 7) / 8, 256>>>(nidx, eidx, out, ninc);
    finalize_kernel<<<1024, 256>>>(out);
}